// round 1
// baseline (speedup 1.0000x reference)
#include <cuda_runtime.h>

// Problem constants (fixed by the dataset)
#define B_    8
#define NQ    1024
#define NK    1024
#define D_    512
#define H_    8
#define HD    64
#define INNER 512          // H_*HD
#define KV_W  1024         // 2*INNER
#define SCALE 0.125f       // 64^-0.5

// Scratch (allocation-free rule: __device__ globals)
__device__ float g_q [B_ * NQ * INNER];          // 16 MB
__device__ float g_kv[B_ * NK * KV_W];           // 32 MB
__device__ float g_ao[B_ * NQ * INNER];          // 16 MB

// ---------------------------------------------------------------------------
// Generic tiled GEMM: C[M,N] = A[M,K] @ B[K,N] (+ bias broadcast over rows)
// 64x64 tile, kstep 16, 256 threads, 4x4 per thread (strided-16 mapping).
// ---------------------------------------------------------------------------
__global__ __launch_bounds__(256) void gemm_kernel(
    const float* __restrict__ A, const float* __restrict__ Bm,
    const float* __restrict__ bias, float* __restrict__ C,
    int M, int N, int K)
{
    __shared__ float As[16][65];   // A tile transposed (k, m), +1 pad
    __shared__ float Bs[16][64];   // B tile (k, n)

    const int tid = threadIdx.x;
    const int tx = tid & 15, ty = tid >> 4;
    const int m0 = blockIdx.y * 64, n0 = blockIdx.x * 64;

    float acc[4][4] = {};

    for (int k0 = 0; k0 < K; k0 += 16) {
        // Load A tile (64 rows x 16 k) as float4, store transposed.
        {
            const int row = tid >> 2, c4 = tid & 3;
            float4 av = *(const float4*)(A + (size_t)(m0 + row) * K + k0 + c4 * 4);
            As[c4 * 4 + 0][row] = av.x;
            As[c4 * 4 + 1][row] = av.y;
            As[c4 * 4 + 2][row] = av.z;
            As[c4 * 4 + 3][row] = av.w;
        }
        // Load B tile (16 k x 64 n) as float4.
        {
            const int kk = tid >> 4, n4 = tid & 15;
            *(float4*)&Bs[kk][n4 * 4] =
                *(const float4*)(Bm + (size_t)(k0 + kk) * N + n0 + n4 * 4);
        }
        __syncthreads();

        #pragma unroll
        for (int kk = 0; kk < 16; kk++) {
            float a[4], b[4];
            #pragma unroll
            for (int ii = 0; ii < 4; ii++) a[ii] = As[kk][ty + 16 * ii];
            #pragma unroll
            for (int jj = 0; jj < 4; jj++) b[jj] = Bs[kk][tx + 16 * jj];
            #pragma unroll
            for (int ii = 0; ii < 4; ii++)
                #pragma unroll
                for (int jj = 0; jj < 4; jj++)
                    acc[ii][jj] += a[ii] * b[jj];
        }
        __syncthreads();
    }

    #pragma unroll
    for (int ii = 0; ii < 4; ii++) {
        const int row = m0 + ty + 16 * ii;
        #pragma unroll
        for (int jj = 0; jj < 4; jj++) {
            const int col = n0 + tx + 16 * jj;
            float v = acc[ii][jj];
            if (bias) v += bias[col];
            C[(size_t)row * N + col] = v;
        }
    }
}

// ---------------------------------------------------------------------------
// Flash-attention style kernel. One block = one (b, h, 64-query tile).
// Online softmax over 16 key tiles of 64. d_head = 64 exactly.
//   q layout:  [B, NQ, INNER]  (head h at column h*64)
//   kv layout: [B, NK, 2*INNER] (k at h*64, v at INNER + h*64)
//   o layout:  [B, NQ, INNER]
// Thread map (16x16): S-tile cols j = tx+16jj; out cols dc = tx*4+jj.
// ---------------------------------------------------------------------------
__global__ __launch_bounds__(256) void attn_kernel(
    const float* __restrict__ q, const float* __restrict__ kv,
    float* __restrict__ o)
{
    __shared__ float Qs[64][64];   // [qrow][d]
    __shared__ float Ks[64][64];   // [key][d], d-groups XOR-swizzled; reused for P (plain)
    __shared__ float Vs[64][64];   // [key][d]

    const int tid = threadIdx.x;
    const int tx = tid & 15, ty = tid >> 4;
    const int bh = blockIdx.y;
    const int b = bh >> 3, h = bh & 7;
    const int q0 = blockIdx.x * 64;

    // Load Q tile (64x64) once.
    const float* qbase = q + (size_t)(b * NQ + q0) * INNER + h * HD;
    #pragma unroll
    for (int r = 0; r < 4; r++) {
        const int f4 = tid + r * 256;          // 0..1023 float4 slots
        const int row = f4 >> 4, c4 = f4 & 15;
        *(float4*)&Qs[row][c4 * 4] =
            *(const float4*)(qbase + (size_t)row * INNER + c4 * 4);
    }

    float m_i[4], l_i[4], acc[4][4] = {};
    #pragma unroll
    for (int ii = 0; ii < 4; ii++) { m_i[ii] = -1e30f; l_i[ii] = 0.0f; }

    const float* kbase = kv + (size_t)(b * NK) * KV_W + h * HD;
    const float* vbase = kbase + INNER;

    for (int t = 0; t < 16; t++) {
        __syncthreads();   // previous P reads / Q load done before overwriting Ks/Vs
        // Load K (swizzled) and V tiles.
        #pragma unroll
        for (int r = 0; r < 4; r++) {
            const int f4 = tid + r * 256;
            const int row = f4 >> 4, c4 = f4 & 15;
            const float* kp = kbase + (size_t)(t * 64 + row) * KV_W + c4 * 4;
            const int sc4 = c4 ^ (row & 15);   // XOR swizzle in float4 units
            *(float4*)&Ks[row][sc4 * 4] = *(const float4*)(kp);
            *(float4*)&Vs[row][c4 * 4]  = *(const float4*)(kp + INNER);
        }
        __syncthreads();

        // S = Q @ K^T (4x4 per thread), vectorized over d in float4 chunks.
        float s[4][4] = {};
        #pragma unroll
        for (int g = 0; g < 16; g++) {
            float4 qa[4], kb[4];
            #pragma unroll
            for (int ii = 0; ii < 4; ii++)
                qa[ii] = *(const float4*)&Qs[ty + 16 * ii][g * 4];
            #pragma unroll
            for (int jj = 0; jj < 4; jj++)
                kb[jj] = *(const float4*)&Ks[tx + 16 * jj][(g ^ tx) * 4];
            #pragma unroll
            for (int ii = 0; ii < 4; ii++)
                #pragma unroll
                for (int jj = 0; jj < 4; jj++)
                    s[ii][jj] += qa[ii].x * kb[jj].x + qa[ii].y * kb[jj].y
                               + qa[ii].z * kb[jj].z + qa[ii].w * kb[jj].w;
        }

        // Online softmax update (row reduction across the 16 tx lanes).
        float p[4][4];
        #pragma unroll
        for (int ii = 0; ii < 4; ii++) {
            #pragma unroll
            for (int jj = 0; jj < 4; jj++) s[ii][jj] *= SCALE;
            float mx = fmaxf(fmaxf(s[ii][0], s[ii][1]), fmaxf(s[ii][2], s[ii][3]));
            #pragma unroll
            for (int off = 8; off >= 1; off >>= 1)
                mx = fmaxf(mx, __shfl_xor_sync(0xffffffffu, mx, off));
            const float mnew = fmaxf(m_i[ii], mx);
            const float corr = __expf(m_i[ii] - mnew);
            float sum = 0.0f;
            #pragma unroll
            for (int jj = 0; jj < 4; jj++) {
                p[ii][jj] = __expf(s[ii][jj] - mnew);
                sum += p[ii][jj];
            }
            #pragma unroll
            for (int off = 8; off >= 1; off >>= 1)
                sum += __shfl_xor_sync(0xffffffffu, sum, off);
            l_i[ii] = l_i[ii] * corr + sum;
            m_i[ii] = mnew;
            #pragma unroll
            for (int jj = 0; jj < 4; jj++) acc[ii][jj] *= corr;
        }

        // Stage P into SMEM (reuse Ks buffer, plain layout).
        __syncthreads();
        #pragma unroll
        for (int ii = 0; ii < 4; ii++)
            #pragma unroll
            for (int jj = 0; jj < 4; jj++)
                Ks[ty + 16 * ii][tx + 16 * jj] = p[ii][jj];
        __syncthreads();

        // acc += P @ V ; thread owns output cols dc = tx*4 + jj.
        #pragma unroll 8
        for (int j = 0; j < 64; j++) {
            float pv[4];
            #pragma unroll
            for (int ii = 0; ii < 4; ii++) pv[ii] = Ks[ty + 16 * ii][j];
            const float4 vv = *(const float4*)&Vs[j][tx * 4];
            #pragma unroll
            for (int ii = 0; ii < 4; ii++) {
                acc[ii][0] += pv[ii] * vv.x;
                acc[ii][1] += pv[ii] * vv.y;
                acc[ii][2] += pv[ii] * vv.z;
                acc[ii][3] += pv[ii] * vv.w;
            }
        }
    }

    // Normalize and store.
    float* obase = o + (size_t)(b * NQ + q0) * INNER + h * HD;
    #pragma unroll
    for (int ii = 0; ii < 4; ii++) {
        const float inv = 1.0f / l_i[ii];
        float4 ov;
        ov.x = acc[ii][0] * inv;
        ov.y = acc[ii][1] * inv;
        ov.z = acc[ii][2] * inv;
        ov.w = acc[ii][3] * inv;
        *(float4*)(obase + (size_t)(ty + 16 * ii) * INNER + tx * 4) = ov;
    }
}

// ---------------------------------------------------------------------------
// Launch: q = x@Wq ; kv = context@Wkv ; attn ; out = ao@Wo + bo
// ---------------------------------------------------------------------------
extern "C" void kernel_launch(void* const* d_in, const int* in_sizes, int n_in,
                              void* d_out, int out_size)
{
    const float* x       = (const float*)d_in[0];   // [8,1024,512]
    const float* context = (const float*)d_in[1];   // [8,1024,512]
    const float* Wq      = (const float*)d_in[2];   // [512,512]
    const float* Wkv     = (const float*)d_in[3];   // [512,1024]
    const float* Wo      = (const float*)d_in[4];   // [512,512]
    const float* bo      = (const float*)d_in[5];   // [512]
    float* out = (float*)d_out;                     // [8,1024,512]

    float *qs, *kvs, *aos;
    cudaGetSymbolAddress((void**)&qs,  g_q);
    cudaGetSymbolAddress((void**)&kvs, g_kv);
    cudaGetSymbolAddress((void**)&aos, g_ao);

    const int Mrows = B_ * NQ;  // 8192

    // q = x @ Wq                 [8192,512] = [8192,512]@[512,512]
    gemm_kernel<<<dim3(INNER / 64, Mrows / 64), 256>>>(x, Wq, nullptr, qs,
                                                       Mrows, INNER, D_);
    // kv = context @ Wkv         [8192,1024] = [8192,512]@[512,1024]
    gemm_kernel<<<dim3(KV_W / 64, Mrows / 64), 256>>>(context, Wkv, nullptr, kvs,
                                                      Mrows, KV_W, D_);
    // attention                  grid: (16 q-tiles, 64 bh pairs)
    attn_kernel<<<dim3(NQ / 64, B_ * H_), 256>>>(qs, kvs, aos);

    // out = ao @ Wo + bo         [8192,512]
    gemm_kernel<<<dim3(D_ / 64, Mrows / 64), 256>>>(aos, Wo, bo, out,
                                                    Mrows, D_, INNER);
}

// round 3
// speedup vs baseline: 1.6458x; 1.6458x over previous
#include <cuda_runtime.h>
#include <cuda_bf16.h>
#include <cstdint>

// ===========================================================================
// Problem constants
// ===========================================================================
#define B_    8
#define NQ    1024
#define NK    1024
#define D_    512
#define H_    8
#define HD    64
#define INNER 512
#define KV_W  1024
#define SCALE 0.125f
#define MROWS (B_ * NQ)          // 8192

// ===========================================================================
// Scratch (__device__ globals; no allocation allowed)
// ===========================================================================
__device__ float g_q [B_ * NQ * INNER];
__device__ float g_kv[B_ * NK * KV_W];
__device__ float g_ao[B_ * NQ * INNER];

__device__ __align__(16) __nv_bfloat16 g_xhi [MROWS * D_],    g_xlo [MROWS * D_];
__device__ __align__(16) __nv_bfloat16 g_chi [MROWS * D_],    g_clo [MROWS * D_];
__device__ __align__(16) __nv_bfloat16 g_aohi[MROWS * INNER], g_aolo[MROWS * INNER];
__device__ __align__(16) __nv_bfloat16 g_wqhi [INNER * D_],   g_wqlo [INNER * D_];   // [N,K]
__device__ __align__(16) __nv_bfloat16 g_wkvhi[KV_W * D_],    g_wkvlo[KV_W * D_];    // [N,K]
__device__ __align__(16) __nv_bfloat16 g_wohi [D_ * INNER],   g_wolo [D_ * INNER];   // [N,K]

// ===========================================================================
// PTX helpers (compute_103-safe: mma.sync / ldmatrix / cp.async only)
// ===========================================================================
__device__ __forceinline__ uint32_t smem_u32(const void* p) {
    uint32_t a;
    asm("{ .reg .u64 t; cvta.to.shared.u64 t, %1; cvt.u32.u64 %0, t; }"
        : "=r"(a) : "l"(p));
    return a;
}
#define CP16(dst_u32, src_ptr) \
    asm volatile("cp.async.cg.shared.global [%0], [%1], 16;" \
                 :: "r"(dst_u32), "l"(src_ptr) : "memory")
#define CP_COMMIT() asm volatile("cp.async.commit_group;" ::: "memory")
#define CP_WAIT(n)  asm volatile("cp.async.wait_group %0;" :: "n"(n) : "memory")

#define LDSM4(r0, r1, r2, r3, addr) \
    asm volatile("ldmatrix.sync.aligned.m8n8.x4.shared.b16 {%0,%1,%2,%3}, [%4];" \
                 : "=r"(r0), "=r"(r1), "=r"(r2), "=r"(r3) : "r"(addr))

#define MMA16816(d, a, b) \
    asm volatile("mma.sync.aligned.m16n8k16.row.col.f32.bf16.bf16.f32 " \
                 "{%0,%1,%2,%3},{%4,%5,%6,%7},{%8,%9},{%0,%1,%2,%3};" \
                 : "+f"((d)[0]), "+f"((d)[1]), "+f"((d)[2]), "+f"((d)[3]) \
                 : "r"((a)[0]), "r"((a)[1]), "r"((a)[2]), "r"((a)[3]), \
                   "r"((b)[0]), "r"((b)[1]))

// ===========================================================================
// HMMA GEMM: C[M,N] = Afp32[M,K] @ W[K,N]  (bf16x3 emulation)
//   A given as (Ahi,Alo) [M,K] row-major bf16
//   B given as (Bhi,Blo) [N,K] row-major bf16 (i.e. W transposed)
// CTA tile 128x128, 8 warps (2x4 of 64x32), K chunk 32, cp.async 2-stage.
// SMEM rows padded to 40 bf16 (80B) -> conflict-free ldmatrix.
// ===========================================================================
#define KC       32
#define ROWB     80                    // padded row bytes (40 bf16)
#define ARR_B    (128 * ROWB)          // 10240 bytes per operand array
#define STAGE_B  (4 * ARR_B)           // 40960 per stage
#define SMEM_TOT (2 * STAGE_B)         // 81920

__global__ __launch_bounds__(256) void gemm_mma(
    const __nv_bfloat16* __restrict__ Ahi, const __nv_bfloat16* __restrict__ Alo,
    const __nv_bfloat16* __restrict__ Bhi, const __nv_bfloat16* __restrict__ Blo,
    const float* __restrict__ bias, float* __restrict__ C,
    int M, int N, int K)
{
    extern __shared__ char sm[];
    const uint32_t sb = smem_u32(sm);
    const int tid = threadIdx.x, lane = tid & 31, warp = tid >> 5;
    const int m0 = blockIdx.y * 128, n0 = blockIdx.x * 128;
    const int wm = (warp >> 2) * 64, wn = (warp & 3) * 32;

    // per-thread stage-load coords: 2 adjacent 16B chunks of one row, per array
    const int ldrow = tid >> 1;               // 0..127
    const int ldcb  = (tid & 1) * 32;          // 0 or 32 (bytes); +16 for second

    auto stage_load = [&](int s, int k0) {
        const uint32_t so = (uint32_t)(s * STAGE_B + ldrow * ROWB + ldcb);
        const size_t ga = ((size_t)(m0 + ldrow) * K + k0) * 2 + ldcb;
        const size_t gb = ((size_t)(n0 + ldrow) * K + k0) * 2 + ldcb;
        CP16(sb + so + 0 * ARR_B,      (const char*)Ahi + ga);
        CP16(sb + so + 0 * ARR_B + 16, (const char*)Ahi + ga + 16);
        CP16(sb + so + 1 * ARR_B,      (const char*)Alo + ga);
        CP16(sb + so + 1 * ARR_B + 16, (const char*)Alo + ga + 16);
        CP16(sb + so + 2 * ARR_B,      (const char*)Bhi + gb);
        CP16(sb + so + 2 * ARR_B + 16, (const char*)Bhi + gb + 16);
        CP16(sb + so + 3 * ARR_B,      (const char*)Blo + gb);
        CP16(sb + so + 3 * ARR_B + 16, (const char*)Blo + gb + 16);
    };

    float acc[4][4][4] = {};

    const int nch = K / KC;
    stage_load(0, 0);
    CP_COMMIT();

    for (int ch = 0; ch < nch; ch++) {
        if (ch + 1 < nch) {
            stage_load((ch + 1) & 1, (ch + 1) * KC);
            CP_COMMIT();
            CP_WAIT(1);
        } else {
            CP_WAIT(0);
        }
        __syncthreads();

        const uint32_t abase = sb + (ch & 1) * STAGE_B;
        const uint32_t bbase = abase + 2 * ARR_B;

        #pragma unroll
        for (int ks = 0; ks < 2; ks++) {
            const int kb = ks * 32;   // k byte offset within 64B of data

            uint32_t ahi[4][4], alo[4][4];
            const uint32_t arow = (uint32_t)(wm + (lane & 15));
            const uint32_t akb  = (uint32_t)(kb + (lane >> 4) * 16);
            #pragma unroll
            for (int mi = 0; mi < 4; mi++) {
                const uint32_t ad = abase + (arow + mi * 16) * ROWB + akb;
                LDSM4(ahi[mi][0], ahi[mi][1], ahi[mi][2], ahi[mi][3], ad);
                LDSM4(alo[mi][0], alo[mi][1], alo[mi][2], alo[mi][3], ad + ARR_B);
            }

            uint32_t bhi[4][2], blo[4][2];
            const uint32_t brow = (uint32_t)(wn + (lane & 7) + ((lane >> 4) & 1) * 8);
            const uint32_t bkb  = (uint32_t)(kb + ((lane >> 3) & 1) * 16);
            #pragma unroll
            for (int nq = 0; nq < 2; nq++) {
                const uint32_t bd = bbase + (brow + nq * 16) * ROWB + bkb;
                uint32_t r0, r1, r2, r3;
                LDSM4(r0, r1, r2, r3, bd);
                bhi[nq * 2][0] = r0; bhi[nq * 2][1] = r1;
                bhi[nq * 2 + 1][0] = r2; bhi[nq * 2 + 1][1] = r3;
                LDSM4(r0, r1, r2, r3, bd + ARR_B);
                blo[nq * 2][0] = r0; blo[nq * 2][1] = r1;
                blo[nq * 2 + 1][0] = r2; blo[nq * 2 + 1][1] = r3;
            }

            #pragma unroll
            for (int mi = 0; mi < 4; mi++)
                #pragma unroll
                for (int ni = 0; ni < 4; ni++) {
                    MMA16816(acc[mi][ni], ahi[mi], bhi[ni]);
                    MMA16816(acc[mi][ni], ahi[mi], blo[ni]);
                    MMA16816(acc[mi][ni], alo[mi], bhi[ni]);
                }
        }
        __syncthreads();
    }

    // epilogue
    #pragma unroll
    for (int mi = 0; mi < 4; mi++) {
        const int r = m0 + wm + mi * 16 + (lane >> 2);
        #pragma unroll
        for (int ni = 0; ni < 4; ni++) {
            const int c = n0 + wn + ni * 8 + (lane & 3) * 2;
            float2 v0 = make_float2(acc[mi][ni][0], acc[mi][ni][1]);
            float2 v1 = make_float2(acc[mi][ni][2], acc[mi][ni][3]);
            if (bias) {
                const float2 b2 = *(const float2*)(bias + c);
                v0.x += b2.x; v0.y += b2.y;
                v1.x += b2.x; v1.y += b2.y;
            }
            *(float2*)(C + (size_t)r * N + c)       = v0;
            *(float2*)(C + (size_t)(r + 8) * N + c) = v1;
        }
    }
}

// ===========================================================================
// fp32 -> (hi, lo) bf16 split, elementwise
// ===========================================================================
__global__ __launch_bounds__(256) void split_kernel(
    const float* __restrict__ in, __nv_bfloat16* __restrict__ hi,
    __nv_bfloat16* __restrict__ lo, int n4)
{
    const int i = blockIdx.x * 256 + threadIdx.x;
    if (i >= n4) return;
    const float4 v = *((const float4*)in + i);
    __nv_bfloat16 h[4], l[4];
    const float f[4] = {v.x, v.y, v.z, v.w};
    #pragma unroll
    for (int j = 0; j < 4; j++) {
        h[j] = __float2bfloat16(f[j]);
        l[j] = __float2bfloat16(f[j] - __bfloat162float(h[j]));
    }
    *((uint2*)hi + i) = *(const uint2*)h;
    *((uint2*)lo + i) = *(const uint2*)l;
}

// ===========================================================================
// W[K,N] -> transposed split: hiT/loT [N,K]
// ===========================================================================
__global__ __launch_bounds__(256) void tsplit_kernel(
    const float* __restrict__ W, __nv_bfloat16* __restrict__ hiT,
    __nv_bfloat16* __restrict__ loT, int K, int N)
{
    __shared__ float t[32][33];
    const int tx = threadIdx.x, ty = threadIdx.y;       // block (32, 8)
    const int c0 = blockIdx.x * 32, r0 = blockIdx.y * 32;
    #pragma unroll
    for (int j = 0; j < 4; j++)
        t[ty + 8 * j][tx] = W[(size_t)(r0 + ty + 8 * j) * N + c0 + tx];
    __syncthreads();
    #pragma unroll
    for (int j = 0; j < 4; j++) {
        const int orow = c0 + ty + 8 * j;   // N index
        const int ocol = r0 + tx;           // K index
        const float v = t[tx][ty + 8 * j];
        const __nv_bfloat16 h = __float2bfloat16(v);
        hiT[(size_t)orow * K + ocol] = h;
        loT[(size_t)orow * K + ocol] = __float2bfloat16(v - __bfloat162float(h));
    }
}

// ===========================================================================
// Flash attention (fp32 SIMT, unchanged from R1 passing kernel)
// ===========================================================================
__global__ __launch_bounds__(256) void attn_kernel(
    const float* __restrict__ q, const float* __restrict__ kv,
    float* __restrict__ o)
{
    __shared__ float Qs[64][64];
    __shared__ float Ks[64][64];
    __shared__ float Vs[64][64];

    const int tid = threadIdx.x;
    const int tx = tid & 15, ty = tid >> 4;
    const int bh = blockIdx.y;
    const int b = bh >> 3, h = bh & 7;
    const int q0 = blockIdx.x * 64;

    const float* qbase = q + (size_t)(b * NQ + q0) * INNER + h * HD;
    #pragma unroll
    for (int r = 0; r < 4; r++) {
        const int f4 = tid + r * 256;
        const int row = f4 >> 4, c4 = f4 & 15;
        *(float4*)&Qs[row][c4 * 4] =
            *(const float4*)(qbase + (size_t)row * INNER + c4 * 4);
    }

    float m_i[4], l_i[4], acc[4][4] = {};
    #pragma unroll
    for (int ii = 0; ii < 4; ii++) { m_i[ii] = -1e30f; l_i[ii] = 0.0f; }

    const float* kbase = kv + (size_t)(b * NK) * KV_W + h * HD;

    for (int t = 0; t < 16; t++) {
        __syncthreads();
        #pragma unroll
        for (int r = 0; r < 4; r++) {
            const int f4 = tid + r * 256;
            const int row = f4 >> 4, c4 = f4 & 15;
            const float* kp = kbase + (size_t)(t * 64 + row) * KV_W + c4 * 4;
            const int sc4 = c4 ^ (row & 15);
            *(float4*)&Ks[row][sc4 * 4] = *(const float4*)(kp);
            *(float4*)&Vs[row][c4 * 4]  = *(const float4*)(kp + INNER);
        }
        __syncthreads();

        float s[4][4] = {};
        #pragma unroll
        for (int g = 0; g < 16; g++) {
            float4 qa[4], kb[4];
            #pragma unroll
            for (int ii = 0; ii < 4; ii++)
                qa[ii] = *(const float4*)&Qs[ty + 16 * ii][g * 4];
            #pragma unroll
            for (int jj = 0; jj < 4; jj++)
                kb[jj] = *(const float4*)&Ks[tx + 16 * jj][(g ^ tx) * 4];
            #pragma unroll
            for (int ii = 0; ii < 4; ii++)
                #pragma unroll
                for (int jj = 0; jj < 4; jj++)
                    s[ii][jj] += qa[ii].x * kb[jj].x + qa[ii].y * kb[jj].y
                               + qa[ii].z * kb[jj].z + qa[ii].w * kb[jj].w;
        }

        float p[4][4];
        #pragma unroll
        for (int ii = 0; ii < 4; ii++) {
            #pragma unroll
            for (int jj = 0; jj < 4; jj++) s[ii][jj] *= SCALE;
            float mx = fmaxf(fmaxf(s[ii][0], s[ii][1]), fmaxf(s[ii][2], s[ii][3]));
            #pragma unroll
            for (int off = 8; off >= 1; off >>= 1)
                mx = fmaxf(mx, __shfl_xor_sync(0xffffffffu, mx, off));
            const float mnew = fmaxf(m_i[ii], mx);
            const float corr = __expf(m_i[ii] - mnew);
            float sum = 0.0f;
            #pragma unroll
            for (int jj = 0; jj < 4; jj++) {
                p[ii][jj] = __expf(s[ii][jj] - mnew);
                sum += p[ii][jj];
            }
            #pragma unroll
            for (int off = 8; off >= 1; off >>= 1)
                sum += __shfl_xor_sync(0xffffffffu, sum, off);
            l_i[ii] = l_i[ii] * corr + sum;
            m_i[ii] = mnew;
            #pragma unroll
            for (int jj = 0; jj < 4; jj++) acc[ii][jj] *= corr;
        }

        __syncthreads();
        #pragma unroll
        for (int ii = 0; ii < 4; ii++)
            #pragma unroll
            for (int jj = 0; jj < 4; jj++)
                Ks[ty + 16 * ii][tx + 16 * jj] = p[ii][jj];
        __syncthreads();

        #pragma unroll 8
        for (int j = 0; j < 64; j++) {
            float pv[4];
            #pragma unroll
            for (int ii = 0; ii < 4; ii++) pv[ii] = Ks[ty + 16 * ii][j];
            const float4 vv = *(const float4*)&Vs[j][tx * 4];
            #pragma unroll
            for (int ii = 0; ii < 4; ii++) {
                acc[ii][0] += pv[ii] * vv.x;
                acc[ii][1] += pv[ii] * vv.y;
                acc[ii][2] += pv[ii] * vv.z;
                acc[ii][3] += pv[ii] * vv.w;
            }
        }
    }

    float* obase = o + (size_t)(b * NQ + q0) * INNER + h * HD;
    #pragma unroll
    for (int ii = 0; ii < 4; ii++) {
        const float inv = 1.0f / l_i[ii];
        float4 ov;
        ov.x = acc[ii][0] * inv;
        ov.y = acc[ii][1] * inv;
        ov.z = acc[ii][2] * inv;
        ov.w = acc[ii][3] * inv;
        *(float4*)(obase + (size_t)(ty + 16 * ii) * INNER + tx * 4) = ov;
    }
}

// ===========================================================================
// Launch
// ===========================================================================
extern "C" void kernel_launch(void* const* d_in, const int* in_sizes, int n_in,
                              void* d_out, int out_size)
{
    const float* x       = (const float*)d_in[0];
    const float* context = (const float*)d_in[1];
    const float* Wq      = (const float*)d_in[2];
    const float* Wkv     = (const float*)d_in[3];
    const float* Wo      = (const float*)d_in[4];
    const float* bo      = (const float*)d_in[5];
    float* out = (float*)d_out;

    float *qs, *kvs, *aos;
    __nv_bfloat16 *xhi, *xlo, *chi, *clo, *aohi, *aolo;
    __nv_bfloat16 *wqhi, *wqlo, *wkvhi, *wkvlo, *wohi, *wolo;
    cudaGetSymbolAddress((void**)&qs,   g_q);
    cudaGetSymbolAddress((void**)&kvs,  g_kv);
    cudaGetSymbolAddress((void**)&aos,  g_ao);
    cudaGetSymbolAddress((void**)&xhi,  g_xhi);   cudaGetSymbolAddress((void**)&xlo,  g_xlo);
    cudaGetSymbolAddress((void**)&chi,  g_chi);   cudaGetSymbolAddress((void**)&clo,  g_clo);
    cudaGetSymbolAddress((void**)&aohi, g_aohi);  cudaGetSymbolAddress((void**)&aolo, g_aolo);
    cudaGetSymbolAddress((void**)&wqhi, g_wqhi);  cudaGetSymbolAddress((void**)&wqlo, g_wqlo);
    cudaGetSymbolAddress((void**)&wkvhi,g_wkvhi); cudaGetSymbolAddress((void**)&wkvlo,g_wkvlo);
    cudaGetSymbolAddress((void**)&wohi, g_wohi);  cudaGetSymbolAddress((void**)&wolo, g_wolo);

    cudaFuncSetAttribute(gemm_mma, cudaFuncAttributeMaxDynamicSharedMemorySize, SMEM_TOT);

    // ---- input splits ----
    const int nx4 = MROWS * D_ / 4;
    split_kernel<<<nx4 / 256, 256>>>(x, xhi, xlo, nx4);
    split_kernel<<<nx4 / 256, 256>>>(context, chi, clo, nx4);
    tsplit_kernel<<<dim3(INNER / 32, D_ / 32), dim3(32, 8)>>>(Wq,  wqhi,  wqlo,  D_, INNER);
    tsplit_kernel<<<dim3(KV_W  / 32, D_ / 32), dim3(32, 8)>>>(Wkv, wkvhi, wkvlo, D_, KV_W);
    tsplit_kernel<<<dim3(D_ / 32, INNER / 32), dim3(32, 8)>>>(Wo,  wohi,  wolo,  INNER, D_);

    // ---- q = x @ Wq ----
    gemm_mma<<<dim3(INNER / 128, MROWS / 128), 256, SMEM_TOT>>>(
        xhi, xlo, wqhi, wqlo, nullptr, qs, MROWS, INNER, D_);
    // ---- kv = context @ Wkv ----
    gemm_mma<<<dim3(KV_W / 128, MROWS / 128), 256, SMEM_TOT>>>(
        chi, clo, wkvhi, wkvlo, nullptr, kvs, MROWS, KV_W, D_);

    // ---- attention ----
    attn_kernel<<<dim3(NQ / 64, B_ * H_), 256>>>(qs, kvs, aos);

    // ---- out = ao @ Wo + bo ----
    const int na4 = MROWS * INNER / 4;
    split_kernel<<<na4 / 256, 256>>>(aos, aohi, aolo, na4);
    gemm_mma<<<dim3(D_ / 128, MROWS / 128), 256, SMEM_TOT>>>(
        aohi, aolo, wohi, wolo, bo, out, MROWS, D_, INNER);
}

// round 4
// speedup vs baseline: 3.9770x; 2.4165x over previous
#include <cuda_runtime.h>
#include <cuda_bf16.h>
#include <cuda_fp16.h>
#include <cstdint>

// ===========================================================================
// Problem constants
// ===========================================================================
#define B_    8
#define NQ    1024
#define NK    1024
#define D_    512
#define H_    8
#define HD    64
#define INNER 512
#define KV_W  1024
#define SCALE 0.125f
#define LOG2E 1.44269504f
#define MROWS (B_ * NQ)          // 8192

// ===========================================================================
// Scratch (__device__ globals)
// ===========================================================================
__device__ __align__(16) __half g_qh [MROWS * INNER];   // q * SCALE*LOG2E, fp16
__device__ __align__(16) __half g_kvh[MROWS * KV_W];    // k,v fp16
__device__ __align__(16) __nv_bfloat16 g_aohi[MROWS * INNER], g_aolo[MROWS * INNER];

__device__ __align__(16) __nv_bfloat16 g_xhi [MROWS * D_],    g_xlo [MROWS * D_];
__device__ __align__(16) __nv_bfloat16 g_chi [MROWS * D_],    g_clo [MROWS * D_];
__device__ __align__(16) __nv_bfloat16 g_wqhi [INNER * D_],   g_wqlo [INNER * D_];
__device__ __align__(16) __nv_bfloat16 g_wkvhi[KV_W * D_],    g_wkvlo[KV_W * D_];
__device__ __align__(16) __nv_bfloat16 g_wohi [D_ * INNER],   g_wolo [D_ * INNER];

// ===========================================================================
// PTX helpers (compute_103-safe)
// ===========================================================================
__device__ __forceinline__ uint32_t smem_u32(const void* p) {
    uint32_t a;
    asm("{ .reg .u64 t; cvta.to.shared.u64 t, %1; cvt.u32.u64 %0, t; }"
        : "=r"(a) : "l"(p));
    return a;
}
#define CP16(dst_u32, src_ptr) \
    asm volatile("cp.async.cg.shared.global [%0], [%1], 16;" \
                 :: "r"(dst_u32), "l"(src_ptr) : "memory")
#define CP_COMMIT() asm volatile("cp.async.commit_group;" ::: "memory")
#define CP_WAIT(n)  asm volatile("cp.async.wait_group %0;" :: "n"(n) : "memory")

#define LDSM4(r0, r1, r2, r3, addr) \
    asm volatile("ldmatrix.sync.aligned.m8n8.x4.shared.b16 {%0,%1,%2,%3}, [%4];" \
                 : "=r"(r0), "=r"(r1), "=r"(r2), "=r"(r3) : "r"(addr))
#define LDSM4T(r0, r1, r2, r3, addr) \
    asm volatile("ldmatrix.sync.aligned.m8n8.x4.trans.shared.b16 {%0,%1,%2,%3}, [%4];" \
                 : "=r"(r0), "=r"(r1), "=r"(r2), "=r"(r3) : "r"(addr))

#define MMA_BF(d, a, b) \
    asm volatile("mma.sync.aligned.m16n8k16.row.col.f32.bf16.bf16.f32 " \
                 "{%0,%1,%2,%3},{%4,%5,%6,%7},{%8,%9},{%0,%1,%2,%3};" \
                 : "+f"((d)[0]), "+f"((d)[1]), "+f"((d)[2]), "+f"((d)[3]) \
                 : "r"((a)[0]), "r"((a)[1]), "r"((a)[2]), "r"((a)[3]), \
                   "r"((b)[0]), "r"((b)[1]))
#define MMA_FP(d, a, b) \
    asm volatile("mma.sync.aligned.m16n8k16.row.col.f32.f16.f16.f32 " \
                 "{%0,%1,%2,%3},{%4,%5,%6,%7},{%8,%9},{%0,%1,%2,%3};" \
                 : "+f"((d)[0]), "+f"((d)[1]), "+f"((d)[2]), "+f"((d)[3]) \
                 : "r"((a)[0]), "r"((a)[1]), "r"((a)[2]), "r"((a)[3]), \
                   "r"((b)[0]), "r"((b)[1]))

__device__ __forceinline__ float ex2f(float x) {
    float y;
    asm("ex2.approx.f32 %0, %1;" : "=f"(y) : "f"(x));
    return y;
}
__device__ __forceinline__ uint32_t pack_h2(float lo, float hi) {
    const __half2 h = __floats2half2_rn(lo, hi);
    return *(const uint32_t*)&h;
}

// ===========================================================================
// HMMA GEMM (bf16x3 emulation), template epilogue.
//   MODE 0: fp32 out (+bias)      MODE 1: fp16 out, scaled by oscale
// ===========================================================================
#define KC       32
#define ROWB     80
#define ARR_B    (128 * ROWB)
#define STAGE_B  (4 * ARR_B)
#define SMEM_TOT (2 * STAGE_B)

template <int MODE>
__global__ __launch_bounds__(256) void gemm_mma(
    const __nv_bfloat16* __restrict__ Ahi, const __nv_bfloat16* __restrict__ Alo,
    const __nv_bfloat16* __restrict__ Bhi, const __nv_bfloat16* __restrict__ Blo,
    const float* __restrict__ bias, void* __restrict__ Cout,
    int M, int N, int K, float oscale)
{
    extern __shared__ char sm[];
    const uint32_t sb = smem_u32(sm);
    const int tid = threadIdx.x, lane = tid & 31, warp = tid >> 5;
    const int m0 = blockIdx.y * 128, n0 = blockIdx.x * 128;
    const int wm = (warp >> 2) * 64, wn = (warp & 3) * 32;

    const int ldrow = tid >> 1;
    const int ldcb  = (tid & 1) * 32;

    auto stage_load = [&](int s, int k0) {
        const uint32_t so = (uint32_t)(s * STAGE_B + ldrow * ROWB + ldcb);
        const size_t ga = ((size_t)(m0 + ldrow) * K + k0) * 2 + ldcb;
        const size_t gb = ((size_t)(n0 + ldrow) * K + k0) * 2 + ldcb;
        CP16(sb + so + 0 * ARR_B,      (const char*)Ahi + ga);
        CP16(sb + so + 0 * ARR_B + 16, (const char*)Ahi + ga + 16);
        CP16(sb + so + 1 * ARR_B,      (const char*)Alo + ga);
        CP16(sb + so + 1 * ARR_B + 16, (const char*)Alo + ga + 16);
        CP16(sb + so + 2 * ARR_B,      (const char*)Bhi + gb);
        CP16(sb + so + 2 * ARR_B + 16, (const char*)Bhi + gb + 16);
        CP16(sb + so + 3 * ARR_B,      (const char*)Blo + gb);
        CP16(sb + so + 3 * ARR_B + 16, (const char*)Blo + gb + 16);
    };

    float acc[4][4][4] = {};
    const int nch = K / KC;
    stage_load(0, 0);
    CP_COMMIT();

    for (int ch = 0; ch < nch; ch++) {
        if (ch + 1 < nch) {
            stage_load((ch + 1) & 1, (ch + 1) * KC);
            CP_COMMIT();
            CP_WAIT(1);
        } else {
            CP_WAIT(0);
        }
        __syncthreads();

        const uint32_t abase = sb + (ch & 1) * STAGE_B;
        const uint32_t bbase = abase + 2 * ARR_B;

        #pragma unroll
        for (int ks = 0; ks < 2; ks++) {
            const int kb = ks * 32;

            uint32_t ahi[4][4], alo[4][4];
            const uint32_t arow = (uint32_t)(wm + (lane & 15));
            const uint32_t akb  = (uint32_t)(kb + (lane >> 4) * 16);
            #pragma unroll
            for (int mi = 0; mi < 4; mi++) {
                const uint32_t ad = abase + (arow + mi * 16) * ROWB + akb;
                LDSM4(ahi[mi][0], ahi[mi][1], ahi[mi][2], ahi[mi][3], ad);
                LDSM4(alo[mi][0], alo[mi][1], alo[mi][2], alo[mi][3], ad + ARR_B);
            }

            uint32_t bhi[4][2], blo[4][2];
            const uint32_t brow = (uint32_t)(wn + (lane & 7) + ((lane >> 4) & 1) * 8);
            const uint32_t bkb  = (uint32_t)(kb + ((lane >> 3) & 1) * 16);
            #pragma unroll
            for (int nq = 0; nq < 2; nq++) {
                const uint32_t bd = bbase + (brow + nq * 16) * ROWB + bkb;
                uint32_t r0, r1, r2, r3;
                LDSM4(r0, r1, r2, r3, bd);
                bhi[nq * 2][0] = r0; bhi[nq * 2][1] = r1;
                bhi[nq * 2 + 1][0] = r2; bhi[nq * 2 + 1][1] = r3;
                LDSM4(r0, r1, r2, r3, bd + ARR_B);
                blo[nq * 2][0] = r0; blo[nq * 2][1] = r1;
                blo[nq * 2 + 1][0] = r2; blo[nq * 2 + 1][1] = r3;
            }

            #pragma unroll
            for (int mi = 0; mi < 4; mi++)
                #pragma unroll
                for (int ni = 0; ni < 4; ni++) {
                    MMA_BF(acc[mi][ni], ahi[mi], bhi[ni]);
                    MMA_BF(acc[mi][ni], ahi[mi], blo[ni]);
                    MMA_BF(acc[mi][ni], alo[mi], bhi[ni]);
                }
        }
        __syncthreads();
    }

    // epilogue
    #pragma unroll
    for (int mi = 0; mi < 4; mi++) {
        const int r = m0 + wm + mi * 16 + (lane >> 2);
        #pragma unroll
        for (int ni = 0; ni < 4; ni++) {
            const int c = n0 + wn + ni * 8 + (lane & 3) * 2;
            if (MODE == 0) {
                float* C = (float*)Cout;
                float2 v0 = make_float2(acc[mi][ni][0], acc[mi][ni][1]);
                float2 v1 = make_float2(acc[mi][ni][2], acc[mi][ni][3]);
                if (bias) {
                    const float2 b2 = *(const float2*)(bias + c);
                    v0.x += b2.x; v0.y += b2.y;
                    v1.x += b2.x; v1.y += b2.y;
                }
                *(float2*)(C + (size_t)r * N + c)       = v0;
                *(float2*)(C + (size_t)(r + 8) * N + c) = v1;
            } else {
                __half* C = (__half*)Cout;
                const __half2 h0 = __floats2half2_rn(acc[mi][ni][0] * oscale,
                                                     acc[mi][ni][1] * oscale);
                const __half2 h1 = __floats2half2_rn(acc[mi][ni][2] * oscale,
                                                     acc[mi][ni][3] * oscale);
                *(__half2*)(C + (size_t)r * N + c)       = h0;
                *(__half2*)(C + (size_t)(r + 8) * N + c) = h1;
            }
        }
    }
}

// ===========================================================================
// splits
// ===========================================================================
__global__ __launch_bounds__(256) void split_kernel(
    const float* __restrict__ in, __nv_bfloat16* __restrict__ hi,
    __nv_bfloat16* __restrict__ lo, int n4)
{
    const int i = blockIdx.x * 256 + threadIdx.x;
    if (i >= n4) return;
    const float4 v = *((const float4*)in + i);
    __nv_bfloat16 h[4], l[4];
    const float f[4] = {v.x, v.y, v.z, v.w};
    #pragma unroll
    for (int j = 0; j < 4; j++) {
        h[j] = __float2bfloat16(f[j]);
        l[j] = __float2bfloat16(f[j] - __bfloat162float(h[j]));
    }
    *((uint2*)hi + i) = *(const uint2*)h;
    *((uint2*)lo + i) = *(const uint2*)l;
}

__global__ __launch_bounds__(256) void tsplit_kernel(
    const float* __restrict__ W, __nv_bfloat16* __restrict__ hiT,
    __nv_bfloat16* __restrict__ loT, int K, int N)
{
    __shared__ float t[32][33];
    const int tx = threadIdx.x, ty = threadIdx.y;
    const int c0 = blockIdx.x * 32, r0 = blockIdx.y * 32;
    #pragma unroll
    for (int j = 0; j < 4; j++)
        t[ty + 8 * j][tx] = W[(size_t)(r0 + ty + 8 * j) * N + c0 + tx];
    __syncthreads();
    #pragma unroll
    for (int j = 0; j < 4; j++) {
        const int orow = c0 + ty + 8 * j;
        const int ocol = r0 + tx;
        const float v = t[tx][ty + 8 * j];
        const __nv_bfloat16 h = __float2bfloat16(v);
        hiT[(size_t)orow * K + ocol] = h;
        loT[(size_t)orow * K + ocol] = __float2bfloat16(v - __bfloat162float(h));
    }
}

// ===========================================================================
// Tensor-core flash attention (fp16 HMMA).
// CTA: 128 q-rows x one (b,h). 8 warps x 16 rows. KV chunk 64, 16 iters.
// q pre-scaled by SCALE*LOG2E -> softmax via ex2.
// Output: bf16 hi/lo split of normalized O.
// ===========================================================================
#define QROWB 144                       // 64 halves (128B) + 16B pad
#define QS_B  (128 * QROWB)             // 18432
#define KVSTG (2 * 64 * QROWB)          // K + V per stage = 18432
#define ATT_SMEM (QS_B + 2 * KVSTG)     // 55296

__global__ __launch_bounds__(256) void attn_mma(
    const __half* __restrict__ qh, const __half* __restrict__ kvh,
    __nv_bfloat16* __restrict__ aohi, __nv_bfloat16* __restrict__ aolo)
{
    extern __shared__ char sm[];
    const uint32_t sb = smem_u32(sm);
    const int tid = threadIdx.x, lane = tid & 31, warp = tid >> 5;
    const int bh = blockIdx.y, b = bh >> 3, h = bh & 7;
    const int q0 = blockIdx.x * 128;

    // ---- Q tile load (group 0) ----
    #pragma unroll
    for (int r = 0; r < 4; r++) {
        const int cid = tid + r * 256;           // 0..1023
        const int row = cid >> 3, ck = cid & 7;
        const char* src = (const char*)(qh + (size_t)(b * NQ + q0 + row) * INNER + h * HD) + ck * 16;
        CP16(sb + row * QROWB + ck * 16, src);
    }
    CP_COMMIT();

    const __half* kbase = kvh + (size_t)(b * NK) * KV_W + h * HD;
    const __half* vbase = kbase + INNER;
    auto kv_stage = [&](int s, int t) {
        const uint32_t so = sb + QS_B + s * KVSTG;
        #pragma unroll
        for (int r = 0; r < 2; r++) {
            const int cid = tid + r * 256;       // 0..511
            const int row = cid >> 3, ck = cid & 7;
            const size_t go = ((size_t)(t * 64 + row) * KV_W + ck * 8) * 2;
            CP16(so + row * QROWB + ck * 16,               (const char*)kbase + go);
            CP16(so + 64 * QROWB + row * QROWB + ck * 16,  (const char*)vbase + go);
        }
    };
    kv_stage(0, 0);
    CP_COMMIT();

    // ---- Q fragments (register-resident for all iterations) ----
    CP_WAIT(1);                 // Q group done
    __syncthreads();
    uint32_t qf[4][4];
    {
        const uint32_t qb = sb + warp * 16 * QROWB;
        #pragma unroll
        for (int ks = 0; ks < 4; ks++) {
            const uint32_t ad = qb + (lane & 15) * QROWB + ks * 32 + (lane >> 4) * 16;
            LDSM4(qf[ks][0], qf[ks][1], qf[ks][2], qf[ks][3], ad);
        }
    }

    float m0r = -1e30f, m1r = -1e30f, l0 = 0.0f, l1 = 0.0f;
    float o[8][4] = {};

    for (int t = 0; t < 16; t++) {
        if (t + 1 < 16) {
            kv_stage((t + 1) & 1, t + 1);
            CP_COMMIT();
            CP_WAIT(1);
        } else {
            CP_WAIT(0);
        }
        __syncthreads();

        const uint32_t kbs = sb + QS_B + (t & 1) * KVSTG;
        const uint32_t vbs = kbs + 64 * QROWB;

        // ---- S = Q @ K^T ----
        float s[8][4] = {};
        #pragma unroll
        for (int ks = 0; ks < 4; ks++) {
            #pragma unroll
            for (int nq = 0; nq < 4; nq++) {
                const uint32_t bd = kbs
                    + (nq * 16 + (lane & 7) + ((lane >> 4) & 1) * 8) * QROWB
                    + ks * 32 + ((lane >> 3) & 1) * 16;
                uint32_t r0, r1, r2, r3;
                LDSM4(r0, r1, r2, r3, bd);
                uint32_t bA[2] = {r0, r1}, bB[2] = {r2, r3};
                MMA_FP(s[nq * 2],     qf[ks], bA);
                MMA_FP(s[nq * 2 + 1], qf[ks], bB);
            }
        }

        // ---- online softmax (log2 domain) ----
        float mx0 = -1e30f, mx1 = -1e30f;
        #pragma unroll
        for (int j = 0; j < 8; j++) {
            mx0 = fmaxf(mx0, fmaxf(s[j][0], s[j][1]));
            mx1 = fmaxf(mx1, fmaxf(s[j][2], s[j][3]));
        }
        mx0 = fmaxf(mx0, __shfl_xor_sync(0xffffffffu, mx0, 1));
        mx0 = fmaxf(mx0, __shfl_xor_sync(0xffffffffu, mx0, 2));
        mx1 = fmaxf(mx1, __shfl_xor_sync(0xffffffffu, mx1, 1));
        mx1 = fmaxf(mx1, __shfl_xor_sync(0xffffffffu, mx1, 2));

        const float nm0 = fmaxf(m0r, mx0), nm1 = fmaxf(m1r, mx1);
        const float c0 = ex2f(m0r - nm0),  c1 = ex2f(m1r - nm1);
        float sum0 = 0.0f, sum1 = 0.0f;
        #pragma unroll
        for (int j = 0; j < 8; j++) {
            s[j][0] = ex2f(s[j][0] - nm0);
            s[j][1] = ex2f(s[j][1] - nm0);
            s[j][2] = ex2f(s[j][2] - nm1);
            s[j][3] = ex2f(s[j][3] - nm1);
            sum0 += s[j][0] + s[j][1];
            sum1 += s[j][2] + s[j][3];
        }
        sum0 += __shfl_xor_sync(0xffffffffu, sum0, 1);
        sum0 += __shfl_xor_sync(0xffffffffu, sum0, 2);
        sum1 += __shfl_xor_sync(0xffffffffu, sum1, 1);
        sum1 += __shfl_xor_sync(0xffffffffu, sum1, 2);

        l0 = l0 * c0 + sum0;  m0r = nm0;
        l1 = l1 * c1 + sum1;  m1r = nm1;
        #pragma unroll
        for (int j = 0; j < 8; j++) {
            o[j][0] *= c0; o[j][1] *= c0;
            o[j][2] *= c1; o[j][3] *= c1;
        }

        // ---- O += P @ V ----
        #pragma unroll
        for (int ks = 0; ks < 4; ks++) {
            uint32_t a[4];
            a[0] = pack_h2(s[2 * ks][0],     s[2 * ks][1]);
            a[1] = pack_h2(s[2 * ks][2],     s[2 * ks][3]);
            a[2] = pack_h2(s[2 * ks + 1][0], s[2 * ks + 1][1]);
            a[3] = pack_h2(s[2 * ks + 1][2], s[2 * ks + 1][3]);
            #pragma unroll
            for (int nb = 0; nb < 4; nb++) {
                const uint32_t vd = vbs
                    + (ks * 16 + (lane & 7) + ((lane >> 3) & 1) * 8) * QROWB
                    + nb * 32 + (lane >> 4) * 16;
                uint32_t r0, r1, r2, r3;
                LDSM4T(r0, r1, r2, r3, vd);
                uint32_t bA[2] = {r0, r1}, bB[2] = {r2, r3};
                MMA_FP(o[nb * 2],     a, bA);
                MMA_FP(o[nb * 2 + 1], a, bB);
            }
        }
        __syncthreads();   // all warps done with this stage before it is refilled
    }

    // ---- epilogue: normalize, bf16 hi/lo split ----
    const float inv0 = 1.0f / l0, inv1 = 1.0f / l1;
    const int row0 = b * NQ + q0 + warp * 16 + (lane >> 2);
    const int colb = h * HD + 2 * (lane & 3);
    #pragma unroll
    for (int j = 0; j < 8; j++) {
        const int c = colb + 8 * j;
        const float f0 = o[j][0] * inv0, f1 = o[j][1] * inv0;
        const float f2 = o[j][2] * inv1, f3 = o[j][3] * inv1;
        __nv_bfloat162 h0, h1, e0, e1;
        h0.x = __float2bfloat16(f0); h0.y = __float2bfloat16(f1);
        h1.x = __float2bfloat16(f2); h1.y = __float2bfloat16(f3);
        e0.x = __float2bfloat16(f0 - __bfloat162float(h0.x));
        e0.y = __float2bfloat16(f1 - __bfloat162float(h0.y));
        e1.x = __float2bfloat16(f2 - __bfloat162float(h1.x));
        e1.y = __float2bfloat16(f3 - __bfloat162float(h1.y));
        *(__nv_bfloat162*)(aohi + (size_t)row0 * INNER + c)       = h0;
        *(__nv_bfloat162*)(aohi + (size_t)(row0 + 8) * INNER + c) = h1;
        *(__nv_bfloat162*)(aolo + (size_t)row0 * INNER + c)       = e0;
        *(__nv_bfloat162*)(aolo + (size_t)(row0 + 8) * INNER + c) = e1;
    }
}

// ===========================================================================
// Launch
// ===========================================================================
extern "C" void kernel_launch(void* const* d_in, const int* in_sizes, int n_in,
                              void* d_out, int out_size)
{
    const float* x       = (const float*)d_in[0];
    const float* context = (const float*)d_in[1];
    const float* Wq      = (const float*)d_in[2];
    const float* Wkv     = (const float*)d_in[3];
    const float* Wo      = (const float*)d_in[4];
    const float* bo      = (const float*)d_in[5];
    float* out = (float*)d_out;

    __half *qhp, *kvhp;
    __nv_bfloat16 *aohi, *aolo;
    __nv_bfloat16 *xhi, *xlo, *chi, *clo;
    __nv_bfloat16 *wqhi, *wqlo, *wkvhi, *wkvlo, *wohi, *wolo;
    cudaGetSymbolAddress((void**)&qhp,  g_qh);
    cudaGetSymbolAddress((void**)&kvhp, g_kvh);
    cudaGetSymbolAddress((void**)&aohi, g_aohi);  cudaGetSymbolAddress((void**)&aolo, g_aolo);
    cudaGetSymbolAddress((void**)&xhi,  g_xhi);   cudaGetSymbolAddress((void**)&xlo,  g_xlo);
    cudaGetSymbolAddress((void**)&chi,  g_chi);   cudaGetSymbolAddress((void**)&clo,  g_clo);
    cudaGetSymbolAddress((void**)&wqhi, g_wqhi);  cudaGetSymbolAddress((void**)&wqlo, g_wqlo);
    cudaGetSymbolAddress((void**)&wkvhi,g_wkvhi); cudaGetSymbolAddress((void**)&wkvlo,g_wkvlo);
    cudaGetSymbolAddress((void**)&wohi, g_wohi);  cudaGetSymbolAddress((void**)&wolo, g_wolo);

    cudaFuncSetAttribute(gemm_mma<0>, cudaFuncAttributeMaxDynamicSharedMemorySize, SMEM_TOT);
    cudaFuncSetAttribute(gemm_mma<1>, cudaFuncAttributeMaxDynamicSharedMemorySize, SMEM_TOT);
    cudaFuncSetAttribute(attn_mma,    cudaFuncAttributeMaxDynamicSharedMemorySize, ATT_SMEM);

    // ---- splits ----
    const int nx4 = MROWS * D_ / 4;
    split_kernel<<<nx4 / 256, 256>>>(x, xhi, xlo, nx4);
    split_kernel<<<nx4 / 256, 256>>>(context, chi, clo, nx4);
    tsplit_kernel<<<dim3(INNER / 32, D_ / 32), dim3(32, 8)>>>(Wq,  wqhi,  wqlo,  D_, INNER);
    tsplit_kernel<<<dim3(KV_W  / 32, D_ / 32), dim3(32, 8)>>>(Wkv, wkvhi, wkvlo, D_, KV_W);
    tsplit_kernel<<<dim3(D_ / 32, INNER / 32), dim3(32, 8)>>>(Wo,  wohi,  wolo,  INNER, D_);

    // ---- projections (fp16 outputs; q pre-scaled into log2 domain) ----
    gemm_mma<1><<<dim3(INNER / 128, MROWS / 128), 256, SMEM_TOT>>>(
        xhi, xlo, wqhi, wqlo, nullptr, qhp, MROWS, INNER, D_, SCALE * LOG2E);
    gemm_mma<1><<<dim3(KV_W / 128, MROWS / 128), 256, SMEM_TOT>>>(
        chi, clo, wkvhi, wkvlo, nullptr, kvhp, MROWS, KV_W, D_, 1.0f);

    // ---- attention ----
    attn_mma<<<dim3(NQ / 128, B_ * H_), 256, ATT_SMEM>>>(qhp, kvhp, aohi, aolo);

    // ---- out = ao @ Wo + bo ----
    gemm_mma<0><<<dim3(D_ / 128, MROWS / 128), 256, SMEM_TOT>>>(
        aohi, aolo, wohi, wolo, bo, out, MROWS, D_, INNER, 1.0f);
}